// round 7
// baseline (speedup 1.0000x reference)
#include <cuda_runtime.h>

// Idx2PixelLayer: bilinear gather of N=1e6 points from a 2048x2048x8 fp32 image.
// c = ((coord - 1) mod (dim - 4)) + 1   (non-negative mod, JAX semantics)
// out = w00*g(0,0) + w10*g(1,0) + w01*g(0,1) + w11*g(1,1)
//   w00=d0*d1, w10=(1-d0)*d1, w01=d0*(1-d1), w11=(1-d0)*(1-d1)
// Reference's off-mask is always false (c <= 2045 < 2048), so dropped.
//
// Layout (best config from R2): 2 threads per point; thread half k (=t&1)
// handles channels 4k..4k+3 -> lane pairs cover one 32B pixel sector per
// gather (1 L1tex wavefront/point/gather), 30 regs, occ ~84%.
//
// R6: TWO HALF-IMAGE PASSES. The full 128MB image + 40MB of streaming traffic
// thrashes the ~126MB L2 (R4's evict_last was neutral; only ~18% of duplicate
// pixel hits are captured). Splitting points by row (i0 < 1024 vs >= 1024)
// makes each pass's image working set 64MB, which fits L2 -> duplicate hits
// become L2 hits, image DRAM reads drop toward unique-block compulsory
// traffic (~99MB total vs ~158MB). Cost: coords read twice (+8MB).

static constexpr int H = 2048;
static constexpr int W = 2048;
static constexpr int C = 8;

__global__ __launch_bounds__(256)
void idx2pixel_kernel(const float* __restrict__ coords,
                      const float* __restrict__ visible,
                      float* __restrict__ out,
                      int n,      // number of points
                      int rlo,    // serve points with rlo <= i0 < rhi
                      int rhi)
{
    int t = blockIdx.x * blockDim.x + threadIdx.x;
    int p = t >> 1;          // point index
    int k = t & 1;           // channel half: floats [4k, 4k+4)
    if (p >= n) return;

    // Both lanes of a pair read the same float2 (broadcast; streaming hint).
    float2 xy = __ldcs(reinterpret_cast<const float2*>(coords) + p);

    const float m0 = (float)(H - 4);   // 2044
    const float m1 = (float)(W - 4);

    float c0 = fmodf(xy.x - 1.0f, m0); if (c0 < 0.0f) c0 += m0; c0 += 1.0f;
    float c1 = fmodf(xy.y - 1.0f, m1); if (c1 < 0.0f) c1 += m1; c1 += 1.0f;

    float f0 = floorf(c0);
    float f1 = floorf(c1);
    float d0 = c0 - f0;
    float d1 = c1 - f1;
    int   i0 = (int)f0;
    int   i1 = (int)f1;

    // Row-range partition: this pass only serves its half of the image,
    // keeping the pass's image working set L2-resident.
    if (i0 < rlo || i0 >= rhi) return;

    // base in floats: pixel (i0,i1), + channel-half offset 4k
    int base = (i0 * W + i1) * C + 4 * k;

    const float4* p00 = reinterpret_cast<const float4*>(visible + base);             // g(0,0)
    const float4* p01 = reinterpret_cast<const float4*>(visible + base + C);         // g(0,1)
    const float4* p10 = reinterpret_cast<const float4*>(visible + base + W * C);     // g(1,0)
    const float4* p11 = reinterpret_cast<const float4*>(visible + base + W * C + C); // g(1,1)

    // Front-batch the 4 gathers for MLP.
    float4 a00 = __ldg(p00);
    float4 a01 = __ldg(p01);
    float4 a10 = __ldg(p10);
    float4 a11 = __ldg(p11);

    float w00 = d0 * d1;
    float w10 = (1.0f - d0) * d1;
    float w01 = d0 * (1.0f - d1);
    float w11 = (1.0f - d0) * (1.0f - d1);

    float4 o;
    o.x = w00 * a00.x + w10 * a10.x + w01 * a01.x + w11 * a11.x;
    o.y = w00 * a00.y + w10 * a10.y + w01 * a01.y + w11 * a11.y;
    o.z = w00 * a00.z + w10 * a10.z + w01 * a01.z + w11 * a11.z;
    o.w = w00 * a00.w + w10 * a10.w + w01 * a01.w + w11 * a11.w;

    // Pair writes one full 32B sector; streaming store (don't pollute L2).
    __stcs(reinterpret_cast<float4*>(out + p * C + 4 * k), o);
}

extern "C" void kernel_launch(void* const* d_in, const int* in_sizes, int n_in,
                              void* d_out, int out_size)
{
    const float* coords  = (const float*)d_in[0];  // [N, 2] fp32
    const float* visible = (const float*)d_in[1];  // [H, W, C] fp32
    float* out = (float*)d_out;                    // [N, C] fp32

    int n = in_sizes[0] / 2;   // number of points
    (void)n_in; (void)out_size;

    int threads = 256;
    int total = 2 * n;         // 2 threads per point
    int blocks = (total + threads - 1) / threads;

    // Pass A: top half of image (rows < 1024, 64MB working set, fits L2).
    idx2pixel_kernel<<<blocks, threads>>>(coords, visible, out, n, 0, 1024);
    // Pass B: bottom half.
    idx2pixel_kernel<<<blocks, threads>>>(coords, visible, out, n, 1024, H);
}

// round 8
// speedup vs baseline: 1.1483x; 1.1483x over previous
#include <cuda_runtime.h>
#include <cstdint>

// Idx2PixelLayer: bilinear gather of N=1e6 points from a 2048x2048x8 fp32 image.
// c = ((coord - 1) mod (dim - 4)) + 1   (non-negative mod, JAX semantics)
// out = w00*g(0,0) + w10*g(1,0) + w01*g(0,1) + w11*g(1,1)
//   w00=d0*d1, w10=(1-d0)*d1, w01=d0*(1-d1), w11=(1-d0)*(1-d1)
// Reference's off-mask is always false (c <= 2045 < 2048), so dropped.
//
// Layout (best from R2): 2 threads per point; thread half k (=t&1) handles
// channels 4k..4k+3 -> each gather covers one 32B pixel sector per lane pair.
//
// R7: PIN HALF THE IMAGE IN L2. R6 proved image reads collapse to compulsory
// when the working set fits L2; R4 proved pinning ALL 128MB thrashes (>126MB
// capacity). So pin exactly the top half (i0 < 1024, 64MB) with an
// L2::evict_last policy; bottom-half gathers use evict_normal. L2 persists
// across graph replays (only L1 flushes per launch), so in steady state the
// top half is permanently resident -> its gathers never touch DRAM. Expected
// DRAM/launch: ~50MB bottom-half unique blocks + 8MB coords + 32MB out.
// Coords/output stay streaming (evict-first) so they can't displace pins.

static constexpr int H = 2048;
static constexpr int W = 2048;
static constexpr int C = 8;

__device__ __forceinline__ float4 ldg_hint_f4(const float4* p, uint64_t pol) {
    float4 v;
    asm volatile("ld.global.nc.L2::cache_hint.v4.f32 {%0,%1,%2,%3}, [%4], %5;"
                 : "=f"(v.x), "=f"(v.y), "=f"(v.z), "=f"(v.w)
                 : "l"(p), "l"(pol));
    return v;
}

__global__ __launch_bounds__(256)
void idx2pixel_kernel(const float* __restrict__ coords,
                      const float* __restrict__ visible,
                      float* __restrict__ out,
                      int n)  // n = number of points
{
    int t = blockIdx.x * blockDim.x + threadIdx.x;
    int p = t >> 1;          // point index
    int k = t & 1;           // channel half: floats [4k, 4k+4)
    if (p >= n) return;

    // Policies: evict_last for the pinned top half, evict_normal otherwise.
    uint64_t polL, polN;
    asm("createpolicy.fractional.L2::evict_last.b64 %0, 1.0;"   : "=l"(polL));
    asm("createpolicy.fractional.L2::evict_normal.b64 %0, 1.0;" : "=l"(polN));

    // Both lanes of a pair read the same float2 (broadcast; streaming hint).
    float2 xy = __ldcs(reinterpret_cast<const float2*>(coords) + p);

    const float m0 = (float)(H - 4);   // 2044
    const float m1 = (float)(W - 4);

    float c0 = fmodf(xy.x - 1.0f, m0); if (c0 < 0.0f) c0 += m0; c0 += 1.0f;
    float c1 = fmodf(xy.y - 1.0f, m1); if (c1 < 0.0f) c1 += m1; c1 += 1.0f;

    float f0 = floorf(c0);
    float f1 = floorf(c1);
    float d0 = c0 - f0;
    float d1 = c1 - f1;
    int   i0 = (int)f0;
    int   i1 = (int)f1;

    // Select cache policy by image half: pin rows [0, 1024) in L2.
    uint64_t pol = (i0 < 1024) ? polL : polN;

    // base in floats: pixel (i0,i1), + channel-half offset 4k
    int base = (i0 * W + i1) * C + 4 * k;

    const float4* p00 = reinterpret_cast<const float4*>(visible + base);             // g(0,0)
    const float4* p01 = reinterpret_cast<const float4*>(visible + base + C);         // g(0,1)
    const float4* p10 = reinterpret_cast<const float4*>(visible + base + W * C);     // g(1,0)
    const float4* p11 = reinterpret_cast<const float4*>(visible + base + W * C + C); // g(1,1)

    // Front-batch the 4 gathers for MLP; per-half L2 policy.
    float4 a00 = ldg_hint_f4(p00, pol);
    float4 a01 = ldg_hint_f4(p01, pol);
    float4 a10 = ldg_hint_f4(p10, pol);
    float4 a11 = ldg_hint_f4(p11, pol);

    float w00 = d0 * d1;
    float w10 = (1.0f - d0) * d1;
    float w01 = d0 * (1.0f - d1);
    float w11 = (1.0f - d0) * (1.0f - d1);

    float4 o;
    o.x = w00 * a00.x + w10 * a10.x + w01 * a01.x + w11 * a11.x;
    o.y = w00 * a00.y + w10 * a10.y + w01 * a01.y + w11 * a11.y;
    o.z = w00 * a00.z + w10 * a10.z + w01 * a01.z + w11 * a11.z;
    o.w = w00 * a00.w + w10 * a10.w + w01 * a01.w + w11 * a11.w;

    // Pair writes one full 32B sector; streaming store (evict-first).
    __stcs(reinterpret_cast<float4*>(out + p * C + 4 * k), o);
}

extern "C" void kernel_launch(void* const* d_in, const int* in_sizes, int n_in,
                              void* d_out, int out_size)
{
    const float* coords  = (const float*)d_in[0];  // [N, 2] fp32
    const float* visible = (const float*)d_in[1];  // [H, W, C] fp32
    float* out = (float*)d_out;                    // [N, C] fp32

    int n = in_sizes[0] / 2;   // number of points
    (void)n_in; (void)out_size;

    int threads = 256;
    int total = 2 * n;         // 2 threads per point
    int blocks = (total + threads - 1) / threads;
    idx2pixel_kernel<<<blocks, threads>>>(coords, visible, out, n);
}